// round 2
// baseline (speedup 1.0000x reference)
#include <cuda_runtime.h>
#include <cstdint>

#define S_LEN 8192
#define C_LEN 24
#define E_DIM 512
#define H_DIM 1024
#define R_DIM 256
#define L_DIM 50
#define GATE_W (4*H_DIM)      // 4096
#define XCAT_DIM (E_DIM+R_DIM) // 768
#define RG 128                 // persistent CTAs for recurrence

// ---------------- static scratch (allocation-free rule) ----------------
__device__ float d_X[(size_t)S_LEN*GATE_W];       // precomputed x-gates + bias, 134MB
__device__ float d_Hs[(size_t)S_LEN*H_DIM];       // word-LSTM hidden states
__device__ float d_gates[(size_t)S_LEN*4*R_DIM];  // char-LSTM gate scratch
__device__ float d_xcat[(size_t)S_LEN*XCAT_DIM];  // [embed | char_rep]
__device__ float d_hchar[(size_t)S_LEN*R_DIM];
__device__ float d_cchar[(size_t)S_LEN*R_DIM];
__device__ float d_hbuf[2*H_DIM];                 // double-buffered word h
__device__ int   d_flags[RG];                     // per-CTA step flags

__device__ __forceinline__ float sigmf(float x){ return 1.f/(1.f+__expf(-x)); }
__device__ __forceinline__ float tanh_fast(float x){
    float e = __expf(-2.f*x);                  // overflow-safe: e=inf -> -1, e=0 -> 1
    return __fdividef(2.f, 1.f + e) - 1.f;
}

// packed f32x2 FMA (FFMA2) — PTX-only path, 2 fp32 MACs per issue slot
__device__ __forceinline__ unsigned long long ffma2(
    unsigned long long a, unsigned long long b, unsigned long long c)
{
    unsigned long long d;
    asm("fma.rn.f32x2 %0, %1, %2, %3;" : "=l"(d) : "l"(a), "l"(b), "l"(c));
    return d;
}

__device__ __forceinline__ int ld_relaxed_gpu(const int* p){
    int v;
    asm volatile("ld.relaxed.gpu.global.s32 %0, [%1];" : "=r"(v) : "l"(p) : "memory");
    return v;
}
__device__ __forceinline__ void st_relaxed_gpu(int* p, int v){
    asm volatile("st.relaxed.gpu.global.s32 [%0], %1;" :: "l"(p), "r"(v) : "memory");
}
__device__ __forceinline__ void fence_gpu(){
    asm volatile("fence.acq_rel.gpu;" ::: "memory");
}

// ---------------- init ----------------
__global__ void init_kernel()
{
    int i = blockIdx.x*blockDim.x + threadIdx.x;
    if (i < RG) d_flags[i] = 0;
    if (i < 2*H_DIM) d_hbuf[i] = 0.f;
    int n = S_LEN*R_DIM;
    for (int k = i; k < n; k += gridDim.x*blockDim.x){
        d_hchar[k] = 0.f;
        d_cchar[k] = 0.f;
    }
}

// ---------------- fp32 tiled GEMM: C[M,N] = A[M,K] * B[N,K]^T (+bias[N]) ----------------
__global__ __launch_bounds__(256) void sgemm_nt(
    const float* __restrict__ A, const float* __restrict__ B,
    float* __restrict__ C, const float* __restrict__ bias,
    int M, int N, int K)
{
    __shared__ float As[16][68];
    __shared__ float Bs[16][68];
    const int bn = blockIdx.x*64, bm = blockIdx.y*64;
    const int tid = threadIdx.x;
    const int tx = tid & 15, ty = tid >> 4;
    const int lr = tid >> 2, lk = (tid & 3) << 2;

    float acc[4][4];
    #pragma unroll
    for (int i=0;i<4;i++)
        #pragma unroll
        for (int j=0;j<4;j++) acc[i][j] = 0.f;

    const float* Ab = A + (size_t)(bm+lr)*K + lk;
    const float* Bb = B + (size_t)(bn+lr)*K + lk;

    for (int k0 = 0; k0 < K; k0 += 16){
        float4 av = *(const float4*)(Ab + k0);
        float4 bv = *(const float4*)(Bb + k0);
        As[lk+0][lr]=av.x; As[lk+1][lr]=av.y; As[lk+2][lr]=av.z; As[lk+3][lr]=av.w;
        Bs[lk+0][lr]=bv.x; Bs[lk+1][lr]=bv.y; Bs[lk+2][lr]=bv.z; Bs[lk+3][lr]=bv.w;
        __syncthreads();
        #pragma unroll
        for (int kk=0;kk<16;kk++){
            float4 a4 = *(const float4*)&As[kk][ty<<2];
            float4 b4 = *(const float4*)&Bs[kk][tx<<2];
            float a[4] = {a4.x,a4.y,a4.z,a4.w};
            float b[4] = {b4.x,b4.y,b4.z,b4.w};
            #pragma unroll
            for (int i=0;i<4;i++)
                #pragma unroll
                for (int j=0;j<4;j++) acc[i][j] = fmaf(a[i], b[j], acc[i][j]);
        }
        __syncthreads();
    }

    #pragma unroll
    for (int i=0;i<4;i++){
        int m = bm + (ty<<2) + i;
        #pragma unroll
        for (int j=0;j<4;j++){
            int n = bn + (tx<<2) + j;
            float v = acc[i][j];
            if (bias) v += bias[n];
            C[(size_t)m*N + n] = v;
        }
    }
}

// ---------------- char-LSTM pointwise update (after gates GEMM) ----------------
__global__ __launch_bounds__(256) void char_update(
    const float* __restrict__ chars,
    const float* __restrict__ Wc_ih,
    const float* __restrict__ bc,
    int step)
{
    int idx = blockIdx.x*blockDim.x + threadIdx.x;
    if (idx >= S_LEN*R_DIM) return;
    int r = idx & (R_DIM-1);
    int s = idx >> 8;
    float x = chars[s*C_LEN + step];
    const float* g = d_gates + (size_t)s*4*R_DIM;
    float gi = g[r]           + Wc_ih[r]          *x + bc[r];
    float gf = g[R_DIM+r]     + Wc_ih[R_DIM+r]    *x + bc[R_DIM+r];
    float gg = g[2*R_DIM+r]   + Wc_ih[2*R_DIM+r]  *x + bc[2*R_DIM+r];
    float go = g[3*R_DIM+r]   + Wc_ih[3*R_DIM+r]  *x + bc[3*R_DIM+r];
    float c = d_cchar[idx];
    c = sigmf(gf)*c + sigmf(gi)*tanh_fast(gg);
    d_cchar[idx] = c;
    d_hchar[idx] = sigmf(go)*tanh_fast(c);
}

// ---------------- embed gather + concat with char_rep ----------------
__global__ __launch_bounds__(256) void gather_concat(
    const int* __restrict__ sentence,
    const float* __restrict__ embed)
{
    int idx = blockIdx.x*blockDim.x + threadIdx.x;
    if (idx >= S_LEN*XCAT_DIM) return;
    int c = idx % XCAT_DIM;
    int s = idx / XCAT_DIM;
    d_xcat[idx] = (c < E_DIM)
        ? embed[(size_t)sentence[s]*E_DIM + c]
        : d_hchar[s*R_DIM + (c - E_DIM)];
}

// ---------------- persistent word-LSTM recurrence ----------------
// 128 CTAs x 512 threads. CTA owns h indices [cta*8, cta*8+8).
// Warp w handles gate rows p0=2w, p1=2w+1 (p = 4*lh + gate).
// FFMA2 packed fp32 GEMV; atomic-free flag barrier, per-warp independent poll.
__global__ __launch_bounds__(512, 1) void word_recur(const float* __restrict__ Whh)
{
    const int cta  = blockIdx.x;
    const int w    = threadIdx.x >> 5;
    const int lane = threadIdx.x & 31;
    const int p0 = 2*w, p1 = 2*w + 1;
    const int lh = p0 >> 2;
    const int g0 = p0 & 3, g1 = p1 & 3;
    const int j0 = g0*H_DIM + cta*8 + lh;
    const int j1 = g1*H_DIM + cta*8 + lh;

    // recurrent weights as packed f32x2 pairs; pair index = lane + 32*i matches h float4 layout
    ulonglong2 w0q[8], w1q[8];
    {
        const ulonglong2* W0 = (const ulonglong2*)(Whh + (size_t)j0*H_DIM);
        const ulonglong2* W1 = (const ulonglong2*)(Whh + (size_t)j1*H_DIM);
        #pragma unroll
        for (int i=0;i<8;i++){ w0q[i] = W0[lane + 32*i]; w1q[i] = W1[lane + 32*i]; }
    }

    __shared__ float gsm[32];
    __shared__ float csm[8];
    if (threadIdx.x < 8) csm[threadIdx.x] = 0.f;
    __syncthreads();

    float xv0 = d_X[j0];
    float xv1 = d_X[j1];

    for (int t = 0; t < S_LEN; t++){
        // prefetch next step's X before the spin — DRAM latency hides under the poll
        float nx0 = 0.f, nx1 = 0.f;
        if (t + 1 < S_LEN){
            nx0 = __ldg(&d_X[(size_t)(t+1)*GATE_W + j0]);
            nx1 = __ldg(&d_X[(size_t)(t+1)*GATE_W + j1]);
        }

        // per-warp independent poll: all CTAs finished step t-1 (flags >= t)
        {
            bool ok;
            do {
                int f0 = ld_relaxed_gpu(&d_flags[lane]);
                int f1 = ld_relaxed_gpu(&d_flags[lane+32]);
                int f2 = ld_relaxed_gpu(&d_flags[lane+64]);
                int f3 = ld_relaxed_gpu(&d_flags[lane+96]);
                int mn = min(min(f0,f1), min(f2,f3));
                ok = __all_sync(0xffffffffu, mn >= t);
            } while(!ok);
            fence_gpu();
        }

        // h broadcast (L2, bypass L1 — buffer alternates each step)
        const float4* h4 = (const float4*)(d_hbuf + (t & 1)*H_DIM);
        float4 hq[8];
        #pragma unroll
        for (int i=0;i<8;i++) hq[i] = __ldcg(h4 + lane + 32*i);

        // packed-fp32 GEMV
        unsigned long long a0a=0ull, a0b=0ull, a1a=0ull, a1b=0ull;
        #pragma unroll
        for (int i=0;i<8;i++){
            ulonglong2 hu = *reinterpret_cast<ulonglong2*>(&hq[i]);
            a0a = ffma2(hu.x, w0q[i].x, a0a);
            a0b = ffma2(hu.y, w0q[i].y, a0b);
            a1a = ffma2(hu.x, w1q[i].x, a1a);
            a1b = ffma2(hu.y, w1q[i].y, a1b);
        }
        float2 f0a = *reinterpret_cast<float2*>(&a0a);
        float2 f0b = *reinterpret_cast<float2*>(&a0b);
        float2 f1a = *reinterpret_cast<float2*>(&a1a);
        float2 f1b = *reinterpret_cast<float2*>(&a1b);
        float a0 = (f0a.x + f0a.y) + (f0b.x + f0b.y);
        float a1 = (f1a.x + f1a.y) + (f1b.x + f1b.y);
        #pragma unroll
        for (int m=16;m>0;m>>=1){
            a0 += __shfl_xor_sync(0xffffffffu, a0, m);
            a1 += __shfl_xor_sync(0xffffffffu, a1, m);
        }
        if (lane == 0){ gsm[p0] = a0 + xv0; gsm[p1] = a1 + xv1; }
        __syncthreads();

        if (w == 0){
            if (lane < 8){
                int l = lane;
                float gi = gsm[4*l+0], gf = gsm[4*l+1], gg = gsm[4*l+2], go = gsm[4*l+3];
                float c = sigmf(gf)*csm[l] + sigmf(gi)*tanh_fast(gg);
                csm[l] = c;
                float hv = sigmf(go)*tanh_fast(c);
                int hidx = cta*8 + l;
                d_hbuf[((t+1) & 1)*H_DIM + hidx] = hv;
                d_Hs[(size_t)t*H_DIM + hidx] = hv;
            }
            __syncwarp();
            if (lane == 0){
                fence_gpu();                         // release h stores
                st_relaxed_gpu(&d_flags[cta], t+1);  // announce step t done
            }
        }

        xv0 = nx0; xv1 = nx1;
    }
}

// ---------------- output layer + log_softmax ----------------
__global__ __launch_bounds__(128) void out_kernel(
    const float* __restrict__ Wout,
    const float* __restrict__ bout,
    float* __restrict__ out)
{
    int s = blockIdx.x;
    __shared__ float hrow[H_DIM];
    __shared__ float e[64];
    __shared__ float s_lse;
    int tid = threadIdx.x;

    const float4* Hs4 = (const float4*)(d_Hs + (size_t)s*H_DIM);
    ((float4*)hrow)[tid*2]   = Hs4[tid*2];
    ((float4*)hrow)[tid*2+1] = Hs4[tid*2+1];
    __syncthreads();

    int warp = tid >> 5, lane = tid & 31;
    for (int l = warp; l < L_DIM; l += 4){
        const float* wr = Wout + (size_t)l*H_DIM;
        float sum = 0.f;
        for (int k = lane; k < H_DIM; k += 32) sum = fmaf(hrow[k], wr[k], sum);
        #pragma unroll
        for (int m=16;m>0;m>>=1) sum += __shfl_xor_sync(0xffffffffu, sum, m);
        if (lane == 0) e[l] = sum + bout[l];
    }
    __syncthreads();

    if (tid < 32){
        float mx = -1e30f;
        for (int l = tid; l < L_DIM; l += 32) mx = fmaxf(mx, e[l]);
        #pragma unroll
        for (int m=16;m>0;m>>=1) mx = fmaxf(mx, __shfl_xor_sync(0xffffffffu, mx, m));
        float sum = 0.f;
        for (int l = tid; l < L_DIM; l += 32) sum += __expf(e[l]-mx);
        #pragma unroll
        for (int m=16;m>0;m>>=1) sum += __shfl_xor_sync(0xffffffffu, sum, m);
        if (tid == 0) s_lse = mx + logf(sum);
    }
    __syncthreads();

    for (int l = tid; l < L_DIM; l += 128)
        out[(size_t)s*L_DIM + l] = e[l] - s_lse;
}

// ---------------- launch ----------------
extern "C" void kernel_launch(void* const* d_in, const int* in_sizes, int n_in,
                              void* d_out, int out_size)
{
    const int*   sentence = (const int*)  d_in[0];
    const float* chars    = (const float*)d_in[1];
    const float* embed    = (const float*)d_in[2];
    const float* Wc_ih    = (const float*)d_in[3];
    const float* Wc_hh    = (const float*)d_in[4];
    const float* bc       = (const float*)d_in[5];
    const float* Ww_ih    = (const float*)d_in[6];
    const float* Ww_hh    = (const float*)d_in[7];
    const float* bw       = (const float*)d_in[8];
    const float* Wout     = (const float*)d_in[9];
    const float* bout     = (const float*)d_in[10];
    float* out = (float*)d_out;

    float *pX, *pGates, *pXcat, *pHchar;
    cudaGetSymbolAddress((void**)&pX,     d_X);
    cudaGetSymbolAddress((void**)&pGates, d_gates);
    cudaGetSymbolAddress((void**)&pXcat,  d_xcat);
    cudaGetSymbolAddress((void**)&pHchar, d_hchar);

    init_kernel<<<1024, 256>>>();

    // char-level LSTM: gates GEMM + pointwise, 24 steps
    dim3 gChar(4*R_DIM/64, S_LEN/64);     // (16, 128)
    int pwBlocks = (S_LEN*R_DIM + 255)/256;
    for (int step = 0; step < C_LEN; step++){
        sgemm_nt<<<gChar, 256>>>(pHchar, Wc_hh, pGates, nullptr,
                                 S_LEN, 4*R_DIM, R_DIM);
        char_update<<<pwBlocks, 256>>>(chars, Wc_ih, bc, step);
    }

    // concat [embed(sentence) | char_rep]
    int gcBlocks = (S_LEN*XCAT_DIM + 255)/256;
    gather_concat<<<gcBlocks, 256>>>(sentence, embed);

    // precompute word-LSTM x-gates: X = xcat @ Ww_ih^T + bw
    dim3 gPre(GATE_W/64, S_LEN/64);       // (64, 128)
    sgemm_nt<<<gPre, 256>>>(pXcat, Ww_ih, pX, bw,
                            S_LEN, GATE_W, XCAT_DIM);

    // sequential word-LSTM recurrence (persistent kernel, flag barrier per step)
    word_recur<<<RG, 512>>>(Ww_hh);

    // output layer + log_softmax
    out_kernel<<<S_LEN, 128>>>(Wout, bout, out);
}

// round 3
// speedup vs baseline: 4.7844x; 4.7844x over previous
#include <cuda_runtime.h>
#include <cstdint>

#define S_LEN 8192
#define C_LEN 24
#define E_DIM 512
#define H_DIM 1024
#define R_DIM 256
#define L_DIM 50
#define GATE_W (4*H_DIM)      // 4096
#define XCAT_DIM (E_DIM+R_DIM) // 768
#define RG 128                 // persistent CTAs for recurrence

// ---------------- static scratch (allocation-free rule) ----------------
__device__ float d_X[(size_t)S_LEN*GATE_W];       // precomputed x-gates + bias
__device__ float d_Hs[(size_t)S_LEN*H_DIM];       // word-LSTM hidden states (also the h pipe)
__device__ float d_gates[(size_t)S_LEN*4*R_DIM];  // char-LSTM gate scratch
__device__ float d_xcat[(size_t)S_LEN*XCAT_DIM];  // [embed | char_rep]
__device__ float d_hchar[(size_t)S_LEN*R_DIM];
__device__ float d_cchar[(size_t)S_LEN*R_DIM];
__device__ float d_h0[H_DIM];                     // zero initial h
__device__ int   d_flags[RG];                     // per-CTA step flags

__device__ __forceinline__ float sigmf(float x){ return 1.f/(1.f+__expf(-x)); }
__device__ __forceinline__ float tanh_fast(float x){
    float e = __expf(-2.f*x);                  // overflow-safe: e=inf -> -1, e=0 -> 1
    return __fdividef(2.f, 1.f + e) - 1.f;
}

// packed f32x2 FMA (FFMA2) — PTX-only path, 2 fp32 MACs per issue slot
__device__ __forceinline__ unsigned long long ffma2(
    unsigned long long a, unsigned long long b, unsigned long long c)
{
    unsigned long long d;
    asm("fma.rn.f32x2 %0, %1, %2, %3;" : "=l"(d) : "l"(a), "l"(b), "l"(c));
    return d;
}

__device__ __forceinline__ int ld_relaxed_gpu(const int* p){
    int v;
    asm volatile("ld.relaxed.gpu.global.s32 %0, [%1];" : "=r"(v) : "l"(p) : "memory");
    return v;
}
__device__ __forceinline__ void st_relaxed_gpu(int* p, int v){
    asm volatile("st.relaxed.gpu.global.s32 [%0], %1;" :: "l"(p), "r"(v) : "memory");
}
__device__ __forceinline__ void fence_gpu(){
    asm volatile("fence.acq_rel.gpu;" ::: "memory");
}

// ---------------- init ----------------
__global__ void init_kernel()
{
    int i = blockIdx.x*blockDim.x + threadIdx.x;
    if (i < RG) d_flags[i] = 0;
    if (i < H_DIM) d_h0[i] = 0.f;
    int n = S_LEN*R_DIM;
    for (int k = i; k < n; k += gridDim.x*blockDim.x){
        d_hchar[k] = 0.f;
        d_cchar[k] = 0.f;
    }
}

// ---------------- fp32 tiled GEMM: C[M,N] = A[M,K] * B[N,K]^T (+bias[N]) ----------------
__global__ __launch_bounds__(256) void sgemm_nt(
    const float* __restrict__ A, const float* __restrict__ B,
    float* __restrict__ C, const float* __restrict__ bias,
    int M, int N, int K)
{
    __shared__ float As[16][68];
    __shared__ float Bs[16][68];
    const int bn = blockIdx.x*64, bm = blockIdx.y*64;
    const int tid = threadIdx.x;
    const int tx = tid & 15, ty = tid >> 4;
    const int lr = tid >> 2, lk = (tid & 3) << 2;

    float acc[4][4];
    #pragma unroll
    for (int i=0;i<4;i++)
        #pragma unroll
        for (int j=0;j<4;j++) acc[i][j] = 0.f;

    const float* Ab = A + (size_t)(bm+lr)*K + lk;
    const float* Bb = B + (size_t)(bn+lr)*K + lk;

    for (int k0 = 0; k0 < K; k0 += 16){
        float4 av = *(const float4*)(Ab + k0);
        float4 bv = *(const float4*)(Bb + k0);
        As[lk+0][lr]=av.x; As[lk+1][lr]=av.y; As[lk+2][lr]=av.z; As[lk+3][lr]=av.w;
        Bs[lk+0][lr]=bv.x; Bs[lk+1][lr]=bv.y; Bs[lk+2][lr]=bv.z; Bs[lk+3][lr]=bv.w;
        __syncthreads();
        #pragma unroll
        for (int kk=0;kk<16;kk++){
            float4 a4 = *(const float4*)&As[kk][ty<<2];
            float4 b4 = *(const float4*)&Bs[kk][tx<<2];
            float a[4] = {a4.x,a4.y,a4.z,a4.w};
            float b[4] = {b4.x,b4.y,b4.z,b4.w};
            #pragma unroll
            for (int i=0;i<4;i++)
                #pragma unroll
                for (int j=0;j<4;j++) acc[i][j] = fmaf(a[i], b[j], acc[i][j]);
        }
        __syncthreads();
    }

    #pragma unroll
    for (int i=0;i<4;i++){
        int m = bm + (ty<<2) + i;
        #pragma unroll
        for (int j=0;j<4;j++){
            int n = bn + (tx<<2) + j;
            float v = acc[i][j];
            if (bias) v += bias[n];
            C[(size_t)m*N + n] = v;
        }
    }
}

// ---------------- char-LSTM pointwise update (after gates GEMM) ----------------
__global__ __launch_bounds__(256) void char_update(
    const float* __restrict__ chars,
    const float* __restrict__ Wc_ih,
    const float* __restrict__ bc,
    int step)
{
    int idx = blockIdx.x*blockDim.x + threadIdx.x;
    if (idx >= S_LEN*R_DIM) return;
    int r = idx & (R_DIM-1);
    int s = idx >> 8;
    float x = chars[s*C_LEN + step];
    const float* g = d_gates + (size_t)s*4*R_DIM;
    float gi = g[r]           + Wc_ih[r]          *x + bc[r];
    float gf = g[R_DIM+r]     + Wc_ih[R_DIM+r]    *x + bc[R_DIM+r];
    float gg = g[2*R_DIM+r]   + Wc_ih[2*R_DIM+r]  *x + bc[2*R_DIM+r];
    float go = g[3*R_DIM+r]   + Wc_ih[3*R_DIM+r]  *x + bc[3*R_DIM+r];
    float c = d_cchar[idx];
    c = sigmf(gf)*c + sigmf(gi)*tanh_fast(gg);
    d_cchar[idx] = c;
    d_hchar[idx] = sigmf(go)*tanh_fast(c);
}

// ---------------- embed gather + concat with char_rep ----------------
__global__ __launch_bounds__(256) void gather_concat(
    const int* __restrict__ sentence,
    const float* __restrict__ embed)
{
    int idx = blockIdx.x*blockDim.x + threadIdx.x;
    if (idx >= S_LEN*XCAT_DIM) return;
    int c = idx % XCAT_DIM;
    int s = idx / XCAT_DIM;
    d_xcat[idx] = (c < E_DIM)
        ? embed[(size_t)sentence[s]*E_DIM + c]
        : d_hchar[s*R_DIM + (c - E_DIM)];
}

// ---------------- persistent word-LSTM recurrence ----------------
// 128 CTAs x 512 threads. CTA owns h indices [cta*8, cta*8+8).
// h of step t lives at d_Hs[t] (fresh address each step -> L1-cached reads are
// never stale; one 4KB L2 fill per CTA per step, 15/16 warps hit L1).
// Barrier: per-CTA flag array, ONLY warp 0 polls (round-2 lesson: poller count).
__global__ __launch_bounds__(512, 1) void word_recur(const float* __restrict__ Whh)
{
    const int cta  = blockIdx.x;
    const int w    = threadIdx.x >> 5;
    const int lane = threadIdx.x & 31;
    const int p0 = 2*w, p1 = 2*w + 1;        // local gate-row ids, p = 4*lh + gate
    const int lh = p0 >> 2;
    const int g0 = p0 & 3, g1 = p1 & 3;
    const int j0 = g0*H_DIM + cta*8 + lh;
    const int j1 = g1*H_DIM + cta*8 + lh;

    // recurrent weights as packed f32x2 pairs; pair index = lane + 32*i matches h float4 layout
    ulonglong2 w0q[8], w1q[8];
    {
        const ulonglong2* W0 = (const ulonglong2*)(Whh + (size_t)j0*H_DIM);
        const ulonglong2* W1 = (const ulonglong2*)(Whh + (size_t)j1*H_DIM);
        #pragma unroll
        for (int i=0;i<8;i++){ w0q[i] = W0[lane + 32*i]; w1q[i] = W1[lane + 32*i]; }
    }

    __shared__ float gsm[32];
    __shared__ float csm[8];
    if (threadIdx.x < 8) csm[threadIdx.x] = 0.f;
    __syncthreads();

    float xv0 = d_X[j0];
    float xv1 = d_X[j1];

    for (int t = 0; t < S_LEN; t++){
        // prefetch next step's X (streaming — don't evict h lines from L1)
        float nx0 = 0.f, nx1 = 0.f;
        if (t + 1 < S_LEN){
            nx0 = __ldcs(&d_X[(size_t)(t+1)*GATE_W + j0]);
            nx1 = __ldcs(&d_X[(size_t)(t+1)*GATE_W + j1]);
        }

        // warp 0 only: poll all 128 flags until every CTA finished step t-1
        if (w == 0){
            bool ok;
            do {
                int f0 = ld_relaxed_gpu(&d_flags[lane]);
                int f1 = ld_relaxed_gpu(&d_flags[lane+32]);
                int f2 = ld_relaxed_gpu(&d_flags[lane+64]);
                int f3 = ld_relaxed_gpu(&d_flags[lane+96]);
                int mn = min(min(f0,f1), min(f2,f3));
                ok = __all_sync(0xffffffffu, mn >= t);
            } while(!ok);
            fence_gpu();     // acquire: order subsequent h loads
        }
        __syncthreads();

        // h of previous step: default cached loads (fresh address -> L1 safe)
        const float4* h4 = (t == 0) ? (const float4*)d_h0
                                    : (const float4*)(d_Hs + (size_t)(t-1)*H_DIM);
        float4 hq[8];
        #pragma unroll
        for (int i=0;i<8;i++) hq[i] = __ldg(h4 + lane + 32*i);

        // packed-fp32 GEMV
        unsigned long long a0a=0ull, a0b=0ull, a1a=0ull, a1b=0ull;
        #pragma unroll
        for (int i=0;i<8;i++){
            ulonglong2 hu = *reinterpret_cast<ulonglong2*>(&hq[i]);
            a0a = ffma2(hu.x, w0q[i].x, a0a);
            a0b = ffma2(hu.y, w0q[i].y, a0b);
            a1a = ffma2(hu.x, w1q[i].x, a1a);
            a1b = ffma2(hu.y, w1q[i].y, a1b);
        }
        float2 f0a = *reinterpret_cast<float2*>(&a0a);
        float2 f0b = *reinterpret_cast<float2*>(&a0b);
        float2 f1a = *reinterpret_cast<float2*>(&a1a);
        float2 f1b = *reinterpret_cast<float2*>(&a1b);
        float a0 = (f0a.x + f0a.y) + (f0b.x + f0b.y);
        float a1 = (f1a.x + f1a.y) + (f1b.x + f1b.y);
        #pragma unroll
        for (int m=16;m>0;m>>=1){
            a0 += __shfl_xor_sync(0xffffffffu, a0, m);
            a1 += __shfl_xor_sync(0xffffffffu, a1, m);
        }
        if (lane == 0){ gsm[p0] = a0 + xv0; gsm[p1] = a1 + xv1; }
        __syncthreads();

        // epilogue + publish (warp 0)
        if (w == 0){
            if (lane < 8){
                int l = lane;
                float gi = gsm[4*l+0], gf = gsm[4*l+1], gg = gsm[4*l+2], go = gsm[4*l+3];
                float c = sigmf(gf)*csm[l] + sigmf(gi)*tanh_fast(gg);
                csm[l] = c;
                float hv = sigmf(go)*tanh_fast(c);
                d_Hs[(size_t)t*H_DIM + cta*8 + l] = hv;
            }
            __syncwarp();
            if (lane == 0){
                fence_gpu();                         // release h stores
                st_relaxed_gpu(&d_flags[cta], t+1);  // announce step t done
            }
        }

        xv0 = nx0; xv1 = nx1;
    }
}

// ---------------- output layer + log_softmax ----------------
__global__ __launch_bounds__(128) void out_kernel(
    const float* __restrict__ Wout,
    const float* __restrict__ bout,
    float* __restrict__ out)
{
    int s = blockIdx.x;
    __shared__ float hrow[H_DIM];
    __shared__ float e[64];
    __shared__ float s_lse;
    int tid = threadIdx.x;

    const float4* Hs4 = (const float4*)(d_Hs + (size_t)s*H_DIM);
    ((float4*)hrow)[tid*2]   = Hs4[tid*2];
    ((float4*)hrow)[tid*2+1] = Hs4[tid*2+1];
    __syncthreads();

    int warp = tid >> 5, lane = tid & 31;
    for (int l = warp; l < L_DIM; l += 4){
        const float* wr = Wout + (size_t)l*H_DIM;
        float sum = 0.f;
        for (int k = lane; k < H_DIM; k += 32) sum = fmaf(hrow[k], wr[k], sum);
        #pragma unroll
        for (int m=16;m>0;m>>=1) sum += __shfl_xor_sync(0xffffffffu, sum, m);
        if (lane == 0) e[l] = sum + bout[l];
    }
    __syncthreads();

    if (tid < 32){
        float mx = -1e30f;
        for (int l = tid; l < L_DIM; l += 32) mx = fmaxf(mx, e[l]);
        #pragma unroll
        for (int m=16;m>0;m>>=1) mx = fmaxf(mx, __shfl_xor_sync(0xffffffffu, mx, m));
        float sum = 0.f;
        for (int l = tid; l < L_DIM; l += 32) sum += __expf(e[l]-mx);
        #pragma unroll
        for (int m=16;m>0;m>>=1) sum += __shfl_xor_sync(0xffffffffu, sum, m);
        if (tid == 0) s_lse = mx + logf(sum);
    }
    __syncthreads();

    for (int l = tid; l < L_DIM; l += 128)
        out[(size_t)s*L_DIM + l] = e[l] - s_lse;
}

// ---------------- launch ----------------
extern "C" void kernel_launch(void* const* d_in, const int* in_sizes, int n_in,
                              void* d_out, int out_size)
{
    const int*   sentence = (const int*)  d_in[0];
    const float* chars    = (const float*)d_in[1];
    const float* embed    = (const float*)d_in[2];
    const float* Wc_ih    = (const float*)d_in[3];
    const float* Wc_hh    = (const float*)d_in[4];
    const float* bc       = (const float*)d_in[5];
    const float* Ww_ih    = (const float*)d_in[6];
    const float* Ww_hh    = (const float*)d_in[7];
    const float* bw       = (const float*)d_in[8];
    const float* Wout     = (const float*)d_in[9];
    const float* bout     = (const float*)d_in[10];
    float* out = (float*)d_out;

    float *pX, *pGates, *pXcat, *pHchar;
    cudaGetSymbolAddress((void**)&pX,     d_X);
    cudaGetSymbolAddress((void**)&pGates, d_gates);
    cudaGetSymbolAddress((void**)&pXcat,  d_xcat);
    cudaGetSymbolAddress((void**)&pHchar, d_hchar);

    init_kernel<<<1024, 256>>>();

    // char-level LSTM: gates GEMM + pointwise, 24 steps
    dim3 gChar(4*R_DIM/64, S_LEN/64);     // (16, 128)
    int pwBlocks = (S_LEN*R_DIM + 255)/256;
    for (int step = 0; step < C_LEN; step++){
        sgemm_nt<<<gChar, 256>>>(pHchar, Wc_hh, pGates, nullptr,
                                 S_LEN, 4*R_DIM, R_DIM);
        char_update<<<pwBlocks, 256>>>(chars, Wc_ih, bc, step);
    }

    // concat [embed(sentence) | char_rep]
    int gcBlocks = (S_LEN*XCAT_DIM + 255)/256;
    gather_concat<<<gcBlocks, 256>>>(sentence, embed);

    // precompute word-LSTM x-gates: X = xcat @ Ww_ih^T + bw
    dim3 gPre(GATE_W/64, S_LEN/64);       // (64, 128)
    sgemm_nt<<<gPre, 256>>>(pXcat, Ww_ih, pX, bw,
                            S_LEN, GATE_W, XCAT_DIM);

    // sequential word-LSTM recurrence (persistent kernel, flag barrier per step)
    word_recur<<<RG, 512>>>(Ww_hh);

    // output layer + log_softmax
    out_kernel<<<S_LEN, 128>>>(Wout, bout, out);
}

// round 5
// speedup vs baseline: 6.5651x; 1.3722x over previous
#include <cuda_runtime.h>
#include <cstdint>

#define S_LEN 8192
#define C_LEN 24
#define E_DIM 512
#define H_DIM 1024
#define R_DIM 256
#define L_DIM 50
#define GATE_W (4*H_DIM)       // 4096
#define XCAT_DIM (E_DIM+R_DIM) // 768
#define RG 128                 // persistent CTAs for recurrence
#define SENT 0x7FC00001u       // NaN-payload sentinel; real h in (-1,1) never equals it

// ---------------- static scratch (allocation-free rule) ----------------
__device__ float d_X[(size_t)S_LEN*GATE_W];       // precomputed x-gates + bias
__device__ float d_Hs[(size_t)S_LEN*H_DIM];       // word-LSTM hidden states (sentinel-filled)
__device__ float d_gates[(size_t)S_LEN*4*R_DIM];  // char-LSTM gate scratch
__device__ float d_xcat[(size_t)S_LEN*XCAT_DIM];  // [embed | char_rep]
__device__ float d_hchar[(size_t)S_LEN*R_DIM];
__device__ float d_cchar[(size_t)S_LEN*R_DIM];

__device__ __forceinline__ float sigmf(float x){ return 1.f/(1.f+__expf(-x)); }
__device__ __forceinline__ float tanh_fast(float x){
    float e = __expf(-2.f*x);                  // overflow-safe: e=inf -> -1, e=0 -> 1
    return __fdividef(2.f, 1.f + e) - 1.f;
}

// packed f32x2 FMA (FFMA2) — PTX-only path, 2 fp32 MACs per issue slot
__device__ __forceinline__ unsigned long long ffma2(
    unsigned long long a, unsigned long long b, unsigned long long c)
{
    unsigned long long d;
    asm("fma.rn.f32x2 %0, %1, %2, %3;" : "=l"(d) : "l"(a), "l"(b), "l"(c));
    return d;
}

// ---------------- init: sentinel-fill d_Hs, zero char states ----------------
__global__ void init_kernel()
{
    int i = blockIdx.x*blockDim.x + threadIdx.x;
    int nth = gridDim.x*blockDim.x;
    uint4* p = (uint4*)d_Hs;
    int n4 = (S_LEN*H_DIM)/4;
    uint4 sv = make_uint4(SENT,SENT,SENT,SENT);
    for (int k = i; k < n4; k += nth) p[k] = sv;
    int n = S_LEN*R_DIM;
    for (int k = i; k < n; k += nth){
        d_hchar[k] = 0.f;
        d_cchar[k] = 0.f;
    }
}

// ---------------- fp32 tiled GEMM: C[M,N] = A[M,K] * B[N,K]^T (+bias[N]) ----------------
__global__ __launch_bounds__(256) void sgemm_nt(
    const float* __restrict__ A, const float* __restrict__ B,
    float* __restrict__ C, const float* __restrict__ bias,
    int M, int N, int K)
{
    __shared__ float As[16][68];
    __shared__ float Bs[16][68];
    const int bn = blockIdx.x*64, bm = blockIdx.y*64;
    const int tid = threadIdx.x;
    const int tx = tid & 15, ty = tid >> 4;
    const int lr = tid >> 2, lk = (tid & 3) << 2;

    float acc[4][4];
    #pragma unroll
    for (int i=0;i<4;i++)
        #pragma unroll
        for (int j=0;j<4;j++) acc[i][j] = 0.f;

    const float* Ab = A + (size_t)(bm+lr)*K + lk;
    const float* Bb = B + (size_t)(bn+lr)*K + lk;

    for (int k0 = 0; k0 < K; k0 += 16){
        float4 av = *(const float4*)(Ab + k0);
        float4 bv = *(const float4*)(Bb + k0);
        As[lk+0][lr]=av.x; As[lk+1][lr]=av.y; As[lk+2][lr]=av.z; As[lk+3][lr]=av.w;
        Bs[lk+0][lr]=bv.x; Bs[lk+1][lr]=bv.y; Bs[lk+2][lr]=bv.z; Bs[lk+3][lr]=bv.w;
        __syncthreads();
        #pragma unroll
        for (int kk=0;kk<16;kk++){
            float4 a4 = *(const float4*)&As[kk][ty<<2];
            float4 b4 = *(const float4*)&Bs[kk][tx<<2];
            float a[4] = {a4.x,a4.y,a4.z,a4.w};
            float b[4] = {b4.x,b4.y,b4.z,b4.w};
            #pragma unroll
            for (int i=0;i<4;i++)
                #pragma unroll
                for (int j=0;j<4;j++) acc[i][j] = fmaf(a[i], b[j], acc[i][j]);
        }
        __syncthreads();
    }

    #pragma unroll
    for (int i=0;i<4;i++){
        int m = bm + (ty<<2) + i;
        #pragma unroll
        for (int j=0;j<4;j++){
            int n = bn + (tx<<2) + j;
            float v = acc[i][j];
            if (bias) v += bias[n];
            C[(size_t)m*N + n] = v;
        }
    }
}

// ---------------- char-LSTM pointwise update (after gates GEMM) ----------------
__global__ __launch_bounds__(256) void char_update(
    const float* __restrict__ chars,
    const float* __restrict__ Wc_ih,
    const float* __restrict__ bc,
    int step)
{
    int idx = blockIdx.x*blockDim.x + threadIdx.x;
    if (idx >= S_LEN*R_DIM) return;
    int r = idx & (R_DIM-1);
    int s = idx >> 8;
    float x = chars[s*C_LEN + step];
    const float* g = d_gates + (size_t)s*4*R_DIM;
    float gi = g[r]           + Wc_ih[r]          *x + bc[r];
    float gf = g[R_DIM+r]     + Wc_ih[R_DIM+r]    *x + bc[R_DIM+r];
    float gg = g[2*R_DIM+r]   + Wc_ih[2*R_DIM+r]  *x + bc[2*R_DIM+r];
    float go = g[3*R_DIM+r]   + Wc_ih[3*R_DIM+r]  *x + bc[3*R_DIM+r];
    float c = d_cchar[idx];
    c = sigmf(gf)*c + sigmf(gi)*tanh_fast(gg);
    d_cchar[idx] = c;
    d_hchar[idx] = sigmf(go)*tanh_fast(c);
}

// ---------------- embed gather + concat with char_rep ----------------
__global__ __launch_bounds__(256) void gather_concat(
    const int* __restrict__ sentence,
    const float* __restrict__ embed)
{
    int idx = blockIdx.x*blockDim.x + threadIdx.x;
    if (idx >= S_LEN*XCAT_DIM) return;
    int c = idx % XCAT_DIM;
    int s = idx / XCAT_DIM;
    d_xcat[idx] = (c < E_DIM)
        ? embed[(size_t)sentence[s]*E_DIM + c]
        : d_hchar[s*R_DIM + (c - E_DIM)];
}

// ---------------- persistent word-LSTM recurrence: sentinel dataflow v2 ----------------
// 128 CTAs x 512 threads. CTA owns h units [cta*8, cta*8+8) => 32 gate rows.
// Warp w computes gate rows p0=2w, p1=2w+1 (p = 4*unit + gate); weights in regs.
// Sync: NO fences/atomics. Warp 15 is the sole poller: polls d_Hs row t-1 (ld.cg),
// relays arrived 16B chunks into smem, re-polls only pending chunks. Each 32-bit
// word is written once (SENT -> value), so checking every word needs no ordering
// assumptions. Warp 0 runs the epilogue and publishes this CTA's 32B h chunk.
__global__ __launch_bounds__(512, 1) void word_recur(const float* __restrict__ Whh)
{
    const int cta  = blockIdx.x;
    const int w    = threadIdx.x >> 5;
    const int lane = threadIdx.x & 31;
    const int p0 = 2*w, p1 = 2*w + 1;        // p = 4*lh + gate
    const int lh = w >> 1;                   // h unit within CTA (0..7)
    const int g0 = p0 & 3, g1 = p1 & 3;
    const int j0 = g0*H_DIM + cta*8 + lh;
    const int j1 = g1*H_DIM + cta*8 + lh;

    // recurrent weights as packed f32x2 pairs; pair index = lane + 32*i matches h float4 layout
    ulonglong2 w0q[8], w1q[8];
    {
        const ulonglong2* W0 = (const ulonglong2*)(Whh + (size_t)j0*H_DIM);
        const ulonglong2* W1 = (const ulonglong2*)(Whh + (size_t)j1*H_DIM);
        #pragma unroll
        for (int i=0;i<8;i++){ w0q[i] = W0[lane + 32*i]; w1q[i] = W1[lane + 32*i]; }
    }

    __shared__ float hsm[H_DIM];   // h(t-1), relayed by poller warp
    __shared__ float gsm[32];      // reduced gate pre-activations
    float cstate = 0.f;            // live in warp 0 lanes 0..7

    // h(-1) = 0
    for (int i = threadIdx.x; i < H_DIM; i += 512) hsm[i] = 0.f;

    float xv0 = d_X[j0];
    float xv1 = d_X[j1];
    __syncthreads();

    for (int t = 0; t < S_LEN; t++){
        // prefetch next step's X (streaming)
        float nx0 = 0.f, nx1 = 0.f;
        if (t + 1 < S_LEN){
            nx0 = __ldcs(&d_X[(size_t)(t+1)*GATE_W + j0]);
            nx1 = __ldcs(&d_X[(size_t)(t+1)*GATE_W + j1]);
        }

        // ---- poller warp: gather h(t-1) into smem (t>0; t==0 uses pre-zeroed hsm) ----
        if (w == 15 && t > 0){
            const uint4* hrow = (const uint4*)(d_Hs + (size_t)(t-1)*H_DIM);
            uint4* hsm4 = (uint4*)hsm;
            unsigned pend = 0xFFu;                     // 8 chunks of 16B per lane
            do {
                #pragma unroll
                for (int k = 0; k < 8; k++){
                    if (pend & (1u<<k)){
                        const uint4* a = hrow + (k*32 + lane);
                        uint4 v;
                        asm volatile("ld.global.cg.v4.u32 {%0,%1,%2,%3}, [%4];"
                            : "=r"(v.x), "=r"(v.y), "=r"(v.z), "=r"(v.w)
                            : "l"(a) : "memory");
                        if (v.x != SENT && v.y != SENT && v.z != SENT && v.w != SENT){
                            hsm4[k*32 + lane] = v;
                            pend &= ~(1u<<k);
                        }
                    }
                }
            } while (__ballot_sync(0xffffffffu, pend != 0u));
        }
        __syncthreads();   // A: hsm complete

        // ---- GEMV from smem (conflict-free LDS.128) ----
        unsigned long long a0a=0ull, a0b=0ull, a1a=0ull, a1b=0ull;
        const float4* h4 = (const float4*)hsm;
        #pragma unroll
        for (int i=0;i<8;i++){
            float4 hv4 = h4[lane + 32*i];
            ulonglong2 hu = *reinterpret_cast<ulonglong2*>(&hv4);
            a0a = ffma2(hu.x, w0q[i].x, a0a);
            a0b = ffma2(hu.y, w0q[i].y, a0b);
            a1a = ffma2(hu.x, w1q[i].x, a1a);
            a1b = ffma2(hu.y, w1q[i].y, a1b);
        }
        float2 f0a = *reinterpret_cast<float2*>(&a0a);
        float2 f0b = *reinterpret_cast<float2*>(&a0b);
        float2 f1a = *reinterpret_cast<float2*>(&a1a);
        float2 f1b = *reinterpret_cast<float2*>(&a1b);
        float a0 = (f0a.x + f0a.y) + (f0b.x + f0b.y);
        float a1 = (f1a.x + f1a.y) + (f1b.x + f1b.y);
        #pragma unroll
        for (int m=16;m>0;m>>=1){
            a0 += __shfl_xor_sync(0xffffffffu, a0, m);
            a1 += __shfl_xor_sync(0xffffffffu, a1, m);
        }
        if (lane == 0){ gsm[p0] = a0 + xv0; gsm[p1] = a1 + xv1; }
        __syncthreads();   // B: gsm ready, hsm reads done

        // ---- epilogue + publish (warp 0) ----
        if (w == 0){
            float hv = 0.f;
            if (lane < 8){
                float4 g4 = *(const float4*)&gsm[4*lane];   // i,f,g,o
                float c = sigmf(g4.y)*cstate + sigmf(g4.x)*tanh_fast(g4.z);
                cstate = c;
                hv = sigmf(g4.w)*tanh_fast(c);
            }
            float v0 = __shfl_sync(0xffffffffu, hv, (lane<<2)+0);
            float v1 = __shfl_sync(0xffffffffu, hv, (lane<<2)+1);
            float v2 = __shfl_sync(0xffffffffu, hv, (lane<<2)+2);
            float v3 = __shfl_sync(0xffffffffu, hv, (lane<<2)+3);
            if (lane < 2){
                float* dst = d_Hs + (size_t)t*H_DIM + cta*8 + lane*4;
                asm volatile("st.global.cg.v4.f32 [%0], {%1,%2,%3,%4};"
                    :: "l"(dst), "f"(v0), "f"(v1), "f"(v2), "f"(v3) : "memory");
            }
        }

        xv0 = nx0; xv1 = nx1;
    }
}

// ---------------- output layer + log_softmax ----------------
__global__ __launch_bounds__(128) void out_kernel(
    const float* __restrict__ Wout,
    const float* __restrict__ bout,
    float* __restrict__ out)
{
    int s = blockIdx.x;
    __shared__ float hrow[H_DIM];
    __shared__ float e[64];
    __shared__ float s_lse;
    int tid = threadIdx.x;

    const float4* Hs4 = (const float4*)(d_Hs + (size_t)s*H_DIM);
    ((float4*)hrow)[tid*2]   = Hs4[tid*2];
    ((float4*)hrow)[tid*2+1] = Hs4[tid*2+1];
    __syncthreads();

    int warp = tid >> 5, lane = tid & 31;
    for (int l = warp; l < L_DIM; l += 4){
        const float* wr = Wout + (size_t)l*H_DIM;
        float sum = 0.f;
        for (int k = lane; k < H_DIM; k += 32) sum = fmaf(hrow[k], wr[k], sum);
        #pragma unroll
        for (int m=16;m>0;m>>=1) sum += __shfl_xor_sync(0xffffffffu, sum, m);
        if (lane == 0) e[l] = sum + bout[l];
    }
    __syncthreads();

    if (tid < 32){
        float mx = -1e30f;
        for (int l = tid; l < L_DIM; l += 32) mx = fmaxf(mx, e[l]);
        #pragma unroll
        for (int m=16;m>0;m>>=1) mx = fmaxf(mx, __shfl_xor_sync(0xffffffffu, mx, m));
        float sum = 0.f;
        for (int l = tid; l < L_DIM; l += 32) sum += __expf(e[l]-mx);
        #pragma unroll
        for (int m=16;m>0;m>>=1) sum += __shfl_xor_sync(0xffffffffu, sum, m);
        if (tid == 0) s_lse = mx + logf(sum);
    }
    __syncthreads();

    for (int l = tid; l < L_DIM; l += 128)
        out[(size_t)s*L_DIM + l] = e[l] - s_lse;
}

// ---------------- launch ----------------
extern "C" void kernel_launch(void* const* d_in, const int* in_sizes, int n_in,
                              void* d_out, int out_size)
{
    const int*   sentence = (const int*)  d_in[0];
    const float* chars    = (const float*)d_in[1];
    const float* embed    = (const float*)d_in[2];
    const float* Wc_ih    = (const float*)d_in[3];
    const float* Wc_hh    = (const float*)d_in[4];
    const float* bc       = (const float*)d_in[5];
    const float* Ww_ih    = (const float*)d_in[6];
    const float* Ww_hh    = (const float*)d_in[7];
    const float* bw       = (const float*)d_in[8];
    const float* Wout     = (const float*)d_in[9];
    const float* bout     = (const float*)d_in[10];
    float* out = (float*)d_out;

    float *pX, *pGates, *pXcat, *pHchar;
    cudaGetSymbolAddress((void**)&pX,     d_X);
    cudaGetSymbolAddress((void**)&pGates, d_gates);
    cudaGetSymbolAddress((void**)&pXcat,  d_xcat);
    cudaGetSymbolAddress((void**)&pHchar, d_hchar);

    init_kernel<<<2048, 256>>>();

    // char-level LSTM: gates GEMM + pointwise, 24 steps
    dim3 gChar(4*R_DIM/64, S_LEN/64);     // (16, 128)
    int pwBlocks = (S_LEN*R_DIM + 255)/256;
    for (int step = 0; step < C_LEN; step++){
        sgemm_nt<<<gChar, 256>>>(pHchar, Wc_hh, pGates, nullptr,
                                 S_LEN, 4*R_DIM, R_DIM);
        char_update<<<pwBlocks, 256>>>(chars, Wc_ih, bc, step);
    }

    // concat [embed(sentence) | char_rep]
    int gcBlocks = (S_LEN*XCAT_DIM + 255)/256;
    gather_concat<<<gcBlocks, 256>>>(sentence, embed);

    // precompute word-LSTM x-gates: X = xcat @ Ww_ih^T + bw
    dim3 gPre(GATE_W/64, S_LEN/64);       // (64, 128)
    sgemm_nt<<<gPre, 256>>>(pXcat, Ww_ih, pX, bw,
                            S_LEN, GATE_W, XCAT_DIM);

    // sequential word-LSTM recurrence (sentinel dataflow v2: single poller warp)
    word_recur<<<RG, 512>>>(Ww_hh);

    // output layer + log_softmax
    out_kernel<<<S_LEN, 128>>>(Wout, bout, out);
}

// round 6
// speedup vs baseline: 7.5743x; 1.1537x over previous
#include <cuda_runtime.h>
#include <cstdint>

#define S_LEN 8192
#define C_LEN 24
#define E_DIM 512
#define H_DIM 1024
#define R_DIM 256
#define L_DIM 50
#define GATE_W (4*H_DIM)       // 4096
#define XCAT_DIM (E_DIM+R_DIM) // 768
#define RG 128                 // persistent CTAs for recurrence
#define SENT 0x7FC00001u       // NaN-payload sentinel; real h in (-1,1) never equals it

// ---------------- static scratch (allocation-free rule) ----------------
__device__ float d_X[(size_t)S_LEN*GATE_W];       // precomputed x-gates + bias
__device__ float d_Hs[(size_t)S_LEN*H_DIM];       // word-LSTM hidden states (sentinel-filled)
__device__ float d_gates[(size_t)S_LEN*4*R_DIM];  // char-LSTM gate scratch
__device__ float d_xcat[(size_t)S_LEN*XCAT_DIM];  // [embed | char_rep]
__device__ float d_hchar[(size_t)S_LEN*R_DIM];
__device__ float d_cchar[(size_t)S_LEN*R_DIM];

__device__ __forceinline__ float sigmf(float x){ return 1.f/(1.f+__expf(-x)); }
__device__ __forceinline__ float tanh_fast(float x){
    float e = __expf(-2.f*x);                  // overflow-safe: e=inf -> -1, e=0 -> 1
    return __fdividef(2.f, 1.f + e) - 1.f;
}

// packed f32x2 FMA (FFMA2) — PTX-only path, 2 fp32 MACs per issue slot
__device__ __forceinline__ unsigned long long ffma2(
    unsigned long long a, unsigned long long b, unsigned long long c)
{
    unsigned long long d;
    asm("fma.rn.f32x2 %0, %1, %2, %3;" : "=l"(d) : "l"(a), "l"(b), "l"(c));
    return d;
}

// ---------------- init: sentinel-fill d_Hs, zero char states ----------------
__global__ void init_kernel()
{
    int i = blockIdx.x*blockDim.x + threadIdx.x;
    int nth = gridDim.x*blockDim.x;
    uint4* p = (uint4*)d_Hs;
    int n4 = (S_LEN*H_DIM)/4;
    uint4 sv = make_uint4(SENT,SENT,SENT,SENT);
    for (int k = i; k < n4; k += nth) p[k] = sv;
    int n = S_LEN*R_DIM;
    for (int k = i; k < n; k += nth){
        d_hchar[k] = 0.f;
        d_cchar[k] = 0.f;
    }
}

// ---------------- fp32 tiled GEMM: C[M,N] = A[M,K] * B[N,K]^T (+bias[N]) ----------------
__global__ __launch_bounds__(256) void sgemm_nt(
    const float* __restrict__ A, const float* __restrict__ B,
    float* __restrict__ C, const float* __restrict__ bias,
    int M, int N, int K)
{
    __shared__ float As[16][68];
    __shared__ float Bs[16][68];
    const int bn = blockIdx.x*64, bm = blockIdx.y*64;
    const int tid = threadIdx.x;
    const int tx = tid & 15, ty = tid >> 4;
    const int lr = tid >> 2, lk = (tid & 3) << 2;

    float acc[4][4];
    #pragma unroll
    for (int i=0;i<4;i++)
        #pragma unroll
        for (int j=0;j<4;j++) acc[i][j] = 0.f;

    const float* Ab = A + (size_t)(bm+lr)*K + lk;
    const float* Bb = B + (size_t)(bn+lr)*K + lk;

    for (int k0 = 0; k0 < K; k0 += 16){
        float4 av = *(const float4*)(Ab + k0);
        float4 bv = *(const float4*)(Bb + k0);
        As[lk+0][lr]=av.x; As[lk+1][lr]=av.y; As[lk+2][lr]=av.z; As[lk+3][lr]=av.w;
        Bs[lk+0][lr]=bv.x; Bs[lk+1][lr]=bv.y; Bs[lk+2][lr]=bv.z; Bs[lk+3][lr]=bv.w;
        __syncthreads();
        #pragma unroll
        for (int kk=0;kk<16;kk++){
            float4 a4 = *(const float4*)&As[kk][ty<<2];
            float4 b4 = *(const float4*)&Bs[kk][tx<<2];
            float a[4] = {a4.x,a4.y,a4.z,a4.w};
            float b[4] = {b4.x,b4.y,b4.z,b4.w};
            #pragma unroll
            for (int i=0;i<4;i++)
                #pragma unroll
                for (int j=0;j<4;j++) acc[i][j] = fmaf(a[i], b[j], acc[i][j]);
        }
        __syncthreads();
    }

    #pragma unroll
    for (int i=0;i<4;i++){
        int m = bm + (ty<<2) + i;
        #pragma unroll
        for (int j=0;j<4;j++){
            int n = bn + (tx<<2) + j;
            float v = acc[i][j];
            if (bias) v += bias[n];
            C[(size_t)m*N + n] = v;
        }
    }
}

// ---------------- char-LSTM pointwise update (after gates GEMM) ----------------
__global__ __launch_bounds__(256) void char_update(
    const float* __restrict__ chars,
    const float* __restrict__ Wc_ih,
    const float* __restrict__ bc,
    int step)
{
    int idx = blockIdx.x*blockDim.x + threadIdx.x;
    if (idx >= S_LEN*R_DIM) return;
    int r = idx & (R_DIM-1);
    int s = idx >> 8;
    float x = chars[s*C_LEN + step];
    const float* g = d_gates + (size_t)s*4*R_DIM;
    float gi = g[r]           + Wc_ih[r]          *x + bc[r];
    float gf = g[R_DIM+r]     + Wc_ih[R_DIM+r]    *x + bc[R_DIM+r];
    float gg = g[2*R_DIM+r]   + Wc_ih[2*R_DIM+r]  *x + bc[2*R_DIM+r];
    float go = g[3*R_DIM+r]   + Wc_ih[3*R_DIM+r]  *x + bc[3*R_DIM+r];
    float c = d_cchar[idx];
    c = sigmf(gf)*c + sigmf(gi)*tanh_fast(gg);
    d_cchar[idx] = c;
    d_hchar[idx] = sigmf(go)*tanh_fast(c);
}

// ---------------- embed gather + concat with char_rep ----------------
__global__ __launch_bounds__(256) void gather_concat(
    const int* __restrict__ sentence,
    const float* __restrict__ embed)
{
    int idx = blockIdx.x*blockDim.x + threadIdx.x;
    if (idx >= S_LEN*XCAT_DIM) return;
    int c = idx % XCAT_DIM;
    int s = idx / XCAT_DIM;
    d_xcat[idx] = (c < E_DIM)
        ? embed[(size_t)sentence[s]*E_DIM + c]
        : d_hchar[s*R_DIM + (c - E_DIM)];
}

// ---------------- persistent word-LSTM recurrence v3 ----------------
// 128 CTAs x 320 threads (10 warps). CTA owns h units [cta*8, cta*8+8).
// Warps 0-7: warp w owns h unit (cta*8+w) = 4 gate rows, weights in regs
//   (128 f32/lane). GEMV from double-buffered smem h, shfl-reduce, lane 0
//   runs the epilogue with persistent c-state and st.cg's ONE h float.
// Warps 8-9: poll d_Hs row t (sentinel dataflow, ld.cg, pending-mask),
//   relay arrived 16B chunks into hsm[(t+1)&1].
// ONE __syncthreads per step (single textual barrier). No fences/atomics:
// every h word is written once (SENT -> value), checked word-by-word.
__global__ __launch_bounds__(320, 1) void word_recur(const float* __restrict__ Whh)
{
    const int cta  = blockIdx.x;
    const int w    = threadIdx.x >> 5;
    const int lane = threadIdx.x & 31;

    __shared__ float hsm[2][H_DIM];   // parity double-buffered h

    for (int i = threadIdx.x; i < H_DIM; i += 320) hsm[0][i] = 0.f;  // h(-1)=0

    // GEMV warps: load weights for rows j_g = g*H_DIM + cta*8 + w
    ulonglong2 wq[4][8];
    float xv[4] = {0.f,0.f,0.f,0.f};
    float cstate = 0.f;
    if (w < 8){
        #pragma unroll
        for (int g=0; g<4; g++){
            const ulonglong2* W = (const ulonglong2*)(Whh + (size_t)(g*H_DIM + cta*8 + w)*H_DIM);
            #pragma unroll
            for (int i=0;i<8;i++) wq[g][i] = W[lane + 32*i];
        }
        if (lane == 0){
            #pragma unroll
            for (int g=0; g<4; g++) xv[g] = d_X[g*H_DIM + cta*8 + w];
        }
    }
    __syncthreads();

    for (int t = 0; t < S_LEN; t++){
        if (w < 8){
            // ---- GEMV over hsm[t&1] ----
            const float4* h4 = (const float4*)hsm[t & 1];
            unsigned long long accA[4] = {0ull,0ull,0ull,0ull};
            unsigned long long accB[4] = {0ull,0ull,0ull,0ull};
            #pragma unroll
            for (int i=0;i<8;i++){
                float4 hv4 = h4[lane + 32*i];
                ulonglong2 hu = *reinterpret_cast<ulonglong2*>(&hv4);
                #pragma unroll
                for (int g=0; g<4; g++){
                    accA[g] = ffma2(hu.x, wq[g][i].x, accA[g]);
                    accB[g] = ffma2(hu.y, wq[g][i].y, accB[g]);
                }
            }
            float s[4];
            #pragma unroll
            for (int g=0; g<4; g++){
                float2 fa = *reinterpret_cast<float2*>(&accA[g]);
                float2 fb = *reinterpret_cast<float2*>(&accB[g]);
                s[g] = (fa.x + fa.y) + (fb.x + fb.y);
            }
            #pragma unroll
            for (int m=16;m>0;m>>=1){
                #pragma unroll
                for (int g=0; g<4; g++)
                    s[g] += __shfl_down_sync(0xffffffffu, s[g], m);
            }
            // ---- epilogue + publish (lane 0 of each GEMV warp) ----
            if (lane == 0){
                float gi = s[0]+xv[0], gf = s[1]+xv[1], gg = s[2]+xv[2], go = s[3]+xv[3];
                float c = sigmf(gf)*cstate + sigmf(gi)*tanh_fast(gg);
                cstate = c;
                float hv = sigmf(go)*tanh_fast(c);
                float* dst = d_Hs + (size_t)t*H_DIM + cta*8 + w;
                asm volatile("st.global.cg.f32 [%0], %1;" :: "l"(dst), "f"(hv) : "memory");
                if (t + 1 < S_LEN){
                    #pragma unroll
                    for (int g=0; g<4; g++)
                        xv[g] = __ldcs(&d_X[(size_t)(t+1)*GATE_W + g*H_DIM + cta*8 + w]);
                }
            }
        } else {
            // ---- poller warps 8,9: gather h(t) into hsm[(t+1)&1] ----
            const int pw = w - 8;                     // 0 or 1, each covers 128 uint4
            const uint4* hrow = (const uint4*)(d_Hs + (size_t)t*H_DIM);
            uint4* dst4 = (uint4*)hsm[(t+1) & 1];
            unsigned pend = 0xFu;                     // 4 chunks of 16B per lane
            do {
                #pragma unroll
                for (int k = 0; k < 4; k++){
                    if (pend & (1u<<k)){
                        int idx = pw*128 + k*32 + lane;
                        uint4 v;
                        asm volatile("ld.global.cg.v4.u32 {%0,%1,%2,%3}, [%4];"
                            : "=r"(v.x), "=r"(v.y), "=r"(v.z), "=r"(v.w)
                            : "l"(hrow + idx) : "memory");
                        if (v.x != SENT && v.y != SENT && v.z != SENT && v.w != SENT){
                            dst4[idx] = v;
                            pend &= ~(1u<<k);
                        }
                    }
                }
            } while (__ballot_sync(0xffffffffu, pend != 0u));
        }
        __syncthreads();   // hsm[(t+1)&1] complete; h(t) published by all warps
    }
}

// ---------------- output layer + log_softmax ----------------
__global__ __launch_bounds__(128) void out_kernel(
    const float* __restrict__ Wout,
    const float* __restrict__ bout,
    float* __restrict__ out)
{
    int s = blockIdx.x;
    __shared__ float hrow[H_DIM];
    __shared__ float e[64];
    __shared__ float s_lse;
    int tid = threadIdx.x;

    const float4* Hs4 = (const float4*)(d_Hs + (size_t)s*H_DIM);
    ((float4*)hrow)[tid*2]   = Hs4[tid*2];
    ((float4*)hrow)[tid*2+1] = Hs4[tid*2+1];
    __syncthreads();

    int warp = tid >> 5, lane = tid & 31;
    for (int l = warp; l < L_DIM; l += 4){
        const float* wr = Wout + (size_t)l*H_DIM;
        float sum = 0.f;
        for (int k = lane; k < H_DIM; k += 32) sum = fmaf(hrow[k], wr[k], sum);
        #pragma unroll
        for (int m=16;m>0;m>>=1) sum += __shfl_xor_sync(0xffffffffu, sum, m);
        if (lane == 0) e[l] = sum + bout[l];
    }
    __syncthreads();

    if (tid < 32){
        float mx = -1e30f;
        for (int l = tid; l < L_DIM; l += 32) mx = fmaxf(mx, e[l]);
        #pragma unroll
        for (int m=16;m>0;m>>=1) mx = fmaxf(mx, __shfl_xor_sync(0xffffffffu, mx, m));
        float sum = 0.f;
        for (int l = tid; l < L_DIM; l += 32) sum += __expf(e[l]-mx);
        #pragma unroll
        for (int m=16;m>0;m>>=1) sum += __shfl_xor_sync(0xffffffffu, sum, m);
        if (tid == 0) s_lse = mx + logf(sum);
    }
    __syncthreads();

    for (int l = tid; l < L_DIM; l += 128)
        out[(size_t)s*L_DIM + l] = e[l] - s_lse;
}

// ---------------- launch ----------------
extern "C" void kernel_launch(void* const* d_in, const int* in_sizes, int n_in,
                              void* d_out, int out_size)
{
    const int*   sentence = (const int*)  d_in[0];
    const float* chars    = (const float*)d_in[1];
    const float* embed    = (const float*)d_in[2];
    const float* Wc_ih    = (const float*)d_in[3];
    const float* Wc_hh    = (const float*)d_in[4];
    const float* bc       = (const float*)d_in[5];
    const float* Ww_ih    = (const float*)d_in[6];
    const float* Ww_hh    = (const float*)d_in[7];
    const float* bw       = (const float*)d_in[8];
    const float* Wout     = (const float*)d_in[9];
    const float* bout     = (const float*)d_in[10];
    float* out = (float*)d_out;

    float *pX, *pGates, *pXcat, *pHchar;
    cudaGetSymbolAddress((void**)&pX,     d_X);
    cudaGetSymbolAddress((void**)&pGates, d_gates);
    cudaGetSymbolAddress((void**)&pXcat,  d_xcat);
    cudaGetSymbolAddress((void**)&pHchar, d_hchar);

    init_kernel<<<2048, 256>>>();

    // char-level LSTM: gates GEMM + pointwise, 24 steps
    dim3 gChar(4*R_DIM/64, S_LEN/64);     // (16, 128)
    int pwBlocks = (S_LEN*R_DIM + 255)/256;
    for (int step = 0; step < C_LEN; step++){
        sgemm_nt<<<gChar, 256>>>(pHchar, Wc_hh, pGates, nullptr,
                                 S_LEN, 4*R_DIM, R_DIM);
        char_update<<<pwBlocks, 256>>>(chars, Wc_ih, bc, step);
    }

    // concat [embed(sentence) | char_rep]
    int gcBlocks = (S_LEN*XCAT_DIM + 255)/256;
    gather_concat<<<gcBlocks, 256>>>(sentence, embed);

    // precompute word-LSTM x-gates: X = xcat @ Ww_ih^T + bw
    dim3 gPre(GATE_W/64, S_LEN/64);       // (64, 128)
    sgemm_nt<<<gPre, 256>>>(pXcat, Ww_ih, pX, bw,
                            S_LEN, GATE_W, XCAT_DIM);

    // sequential word-LSTM recurrence (sentinel dataflow v3)
    word_recur<<<RG, 320>>>(Ww_hh);

    // output layer + log_softmax
    out_kernel<<<S_LEN, 128>>>(Wout, bout, out);
}